// round 6
// baseline (speedup 1.0000x reference)
#include <cuda_runtime.h>
#include <cuda_bf16.h>
#include <cstdint>
#include <math.h>

#define NN 100000
#define NE 1600000
#define SCAN_B 98   // ceil(NN/1024)

// ---------------- scratch (static device memory; no allocations) ----------------
__device__ int   g_is64;
__device__ int   g_deg[NN];
__device__ int   g_incl[NN];
__device__ int   g_bsum[SCAN_B];
__device__ int   g_off[NN + 1];
__device__ int   g_cur[NN];
__device__ int   g_srcs[NE];
__device__ float g_h1[NN * 64];
__device__ float g_s1[NN * 8];
__device__ float g_t1[NN * 8];
__device__ float g_z [NN * 64];
__device__ float g_h2[NN * 16];
__device__ float g_s2[NN];
__device__ float g_t2[NN];

// ---------------- init: zero counters + detect edge dtype (int64 vs int32) ----------------
__global__ void k_init(const int* __restrict__ w) {
    int i = blockIdx.x * blockDim.x + threadIdx.x;
    if (i < NN) { g_deg[i] = 0; g_cur[i] = 0; }
    if (i == 0) {
        int is64 = 1;
        #pragma unroll
        for (int k = 0; k < 8; k++)
            if (w[2 * k + 1] != 0) is64 = 0;
        g_is64 = is64;
    }
}

__global__ void k_hist(const int* __restrict__ w) {
    int i = blockIdx.x * blockDim.x + threadIdx.x;
    if (i >= NE) return;
    long long di = g_is64 ? 2LL * (NE + (long long)i) : (long long)(NE + i);
    atomicAdd(&g_deg[w[di]], 1);
}

__global__ void k_scanA() {
    __shared__ int sh[1024];
    int i = blockIdx.x * 1024 + threadIdx.x;
    int v = (i < NN) ? g_deg[i] : 0;
    sh[threadIdx.x] = v;
    __syncthreads();
    #pragma unroll
    for (int ofs = 1; ofs < 1024; ofs <<= 1) {
        int add = (threadIdx.x >= ofs) ? sh[threadIdx.x - ofs] : 0;
        __syncthreads();
        sh[threadIdx.x] += add;
        __syncthreads();
    }
    if (i < NN) g_incl[i] = sh[threadIdx.x];
    if (threadIdx.x == 1023) g_bsum[blockIdx.x] = sh[1023];
}

// fused: every block redundantly scans the 98 block sums (400B of L2 reads),
// then writes its slice of g_off. Replaces separate scanB + scanC kernels.
__global__ void k_scanC() {
    __shared__ int sh[256];
    __shared__ int boff_s[256];
    int t = threadIdx.x;
    int v = (t < SCAN_B) ? g_bsum[t] : 0;
    sh[t] = v;
    __syncthreads();
    #pragma unroll
    for (int ofs = 1; ofs < 256; ofs <<= 1) {
        int add = (t >= ofs) ? sh[t - ofs] : 0;
        __syncthreads();
        sh[t] += add;
        __syncthreads();
    }
    boff_s[t] = sh[t] - v;    // exclusive prefix of block sums
    __syncthreads();

    int i = blockIdx.x * 256 + t;
    if (i < NN) g_off[i + 1] = g_incl[i] + boff_s[i >> 10];
    if (i == 0) g_off[0] = 0;
}

__global__ void k_scatter(const int* __restrict__ w) {
    int i = blockIdx.x * blockDim.x + threadIdx.x;
    if (i >= NE) return;
    int is64 = g_is64;
    int s = w[is64 ? 2LL * i : (long long)i];
    int d = w[is64 ? 2LL * (NE + (long long)i) : (long long)(NE + i)];
    int pos = g_off[d] + atomicAdd(&g_cur[d], 1);
    g_srcs[pos] = s;
}

// ---------------- GEMM1: h1 = x @ W1 (+ s1/t1 epilogue), packed f32x2 FFMA ----------------
// Tile: 128 rows x 64 cols per block, K-tiles of 32, two k's per inner step (LDS.128).
// xs rows padded to 34 ull (272B, 16B-aligned) so &xs[row][even k] is 16B-aligned.
__global__ __launch_bounds__(128, 4) void k_gemm1(
    const float* __restrict__ x, const float* __restrict__ W1,
    const float* __restrict__ a1s, const float* __restrict__ a1d)
{
    __shared__ __align__(16) unsigned long long xs[128][34];  // x duplicated into both f32x2 halves
    __shared__ __align__(16) float ws[32][64];
    const int t = threadIdx.x;
    const int rowblk = blockIdx.x * 128;
    const int tr = t >> 3;   // 0..15
    const int tc = t & 7;    // 0..7 (head)

    unsigned long long acc[8][4];
    #pragma unroll
    for (int r = 0; r < 8; r++)
        #pragma unroll
        for (int j = 0; j < 4; j++) acc[r][j] = 0ULL;

    for (int k0 = 0; k0 < 256; k0 += 32) {
        #pragma unroll
        for (int r = 0; r < 32; r++) {
            int row = (r << 2) + (t >> 5);
            int grow = rowblk + row;
            float v = (grow < NN) ? x[grow * 256 + k0 + (t & 31)] : 0.f;
            unsigned long long p;
            asm("mov.b64 %0, {%1, %1};" : "=l"(p) : "f"(v));
            xs[row][t & 31] = p;
        }
        #pragma unroll
        for (int r = 0; r < 16; r++) {
            int idx = (r << 7) + t;
            ws[idx >> 6][idx & 63] = W1[(k0 + (idx >> 6)) * 64 + (idx & 63)];
        }
        __syncthreads();
        #pragma unroll 4
        for (int k = 0; k < 32; k += 2) {
            const ulonglong2* bp0 = (const ulonglong2*)&ws[k][tc << 3];
            const ulonglong2* bp1 = (const ulonglong2*)&ws[k + 1][tc << 3];
            ulonglong2 b00 = bp0[0], b01 = bp0[1];
            ulonglong2 b10 = bp1[0], b11 = bp1[1];
            #pragma unroll
            for (int r = 0; r < 8; r++) {
                ulonglong2 a2 = *(const ulonglong2*)&xs[tr + (r << 4)][k];
                asm("fma.rn.f32x2 %0, %4, %5, %0;\n\t"
                    "fma.rn.f32x2 %1, %4, %6, %1;\n\t"
                    "fma.rn.f32x2 %2, %4, %7, %2;\n\t"
                    "fma.rn.f32x2 %3, %4, %8, %3;"
                    : "+l"(acc[r][0]), "+l"(acc[r][1]), "+l"(acc[r][2]), "+l"(acc[r][3])
                    : "l"(a2.x), "l"(b00.x), "l"(b00.y), "l"(b01.x), "l"(b01.y));
                asm("fma.rn.f32x2 %0, %4, %5, %0;\n\t"
                    "fma.rn.f32x2 %1, %4, %6, %1;\n\t"
                    "fma.rn.f32x2 %2, %4, %7, %2;\n\t"
                    "fma.rn.f32x2 %3, %4, %8, %3;"
                    : "+l"(acc[r][0]), "+l"(acc[r][1]), "+l"(acc[r][2]), "+l"(acc[r][3])
                    : "l"(a2.y), "l"(b10.x), "l"(b10.y), "l"(b11.x), "l"(b11.y));
            }
        }
        __syncthreads();
    }

    float av[8], bv[8];
    #pragma unroll
    for (int d = 0; d < 8; d++) { av[d] = a1s[(tc << 3) + d]; bv[d] = a1d[(tc << 3) + d]; }
    #pragma unroll
    for (int r = 0; r < 8; r++) {
        int grow = rowblk + tr + (r << 4);
        if (grow >= NN) continue;
        float s = 0.f, tt = 0.f;
        float2* hp = (float2*)&g_h1[grow * 64 + (tc << 3)];
        #pragma unroll
        for (int j = 0; j < 4; j++) {
            unsigned long long u = acc[r][j];
            float lo = __uint_as_float((unsigned)u);
            float hi = __uint_as_float((unsigned)(u >> 32));
            hp[j] = make_float2(lo, hi);
            s  += lo * av[2 * j] + hi * av[2 * j + 1];
            tt += lo * bv[2 * j] + hi * bv[2 * j + 1];
        }
        g_s1[grow * 8 + tc] = s;
        g_t1[grow * 8 + tc] = tt;
    }
}

// ---------------- Layer-1 aggregation: warp per dst node ----------------
// Plain exp (no running max): logits bounded -> unshifted softmax identical.
__global__ void k_agg1() {
    int n = (blockIdx.x * blockDim.x + threadIdx.x) >> 5;
    if (n >= NN) return;
    const int lane = threadIdx.x & 31;
    const int h  = lane >> 2;                     // head 0..7
    const int ch = (h << 3) + ((lane & 3) << 1);  // first channel of the pair

    const float tn = g_t1[n * 8 + h];
    const int j0 = g_off[n], j1 = g_off[n + 1];

    float d = 0.f, Ax = 0.f, Ay = 0.f;
    #pragma unroll 4
    for (int j = j0; j < j1; j++) {
        int src = __ldg(&g_srcs[j]);
        float e = __ldg(&g_s1[src * 8 + h]) + tn;
        e = e > 0.f ? e : 0.2f * e;
        float p = __expf(e);
        float2 hv = *(const float2*)&g_h1[src * 64 + ch];
        d += p;
        Ax += p * hv.x;
        Ay += p * hv.y;
    }
    float inv = 1.f / (d + 1e-16f);
    float r0 = Ax * inv, r1 = Ay * inv;
    float2 zo;
    zo.x = r0 > 0.f ? r0 : expm1f(r0);   // elu
    zo.y = r1 > 0.f ? r1 : expm1f(r1);
    *(float2*)&g_z[n * 64 + ch] = zo;
}

// ---------------- GEMM2: h2 = z @ W2 (+ s2/t2 epilogue) ----------------
__global__ __launch_bounds__(128) void k_gemm2(
    const float* __restrict__ W2, const float* __restrict__ a2s, const float* __restrict__ a2d)
{
    __shared__ float zs[128][65];
    __shared__ __align__(16) float w2s[1024];
    const int t = threadIdx.x;
    const int base = blockIdx.x * 128;

    #pragma unroll
    for (int r = 0; r < 64; r++) {
        int i = (r << 7) + t;
        int row = i >> 6, col = i & 63;
        int grow = base + row;
        zs[row][col] = (grow < NN) ? g_z[grow * 64 + col] : 0.f;
    }
    #pragma unroll
    for (int r = 0; r < 8; r++) w2s[(r << 7) + t] = W2[(r << 7) + t];
    __syncthreads();

    int row = base + t;
    if (row >= NN) return;

    float acc[16];
    #pragma unroll
    for (int c = 0; c < 16; c++) acc[c] = 0.f;

    #pragma unroll 8
    for (int k = 0; k < 64; k++) {
        float a = zs[t][k];
        const float4* wp = (const float4*)&w2s[k << 4];
        float4 w0 = wp[0], w1 = wp[1], w2 = wp[2], w3 = wp[3];
        acc[0]  += a * w0.x; acc[1]  += a * w0.y; acc[2]  += a * w0.z; acc[3]  += a * w0.w;
        acc[4]  += a * w1.x; acc[5]  += a * w1.y; acc[6]  += a * w1.z; acc[7]  += a * w1.w;
        acc[8]  += a * w2.x; acc[9]  += a * w2.y; acc[10] += a * w2.z; acc[11] += a * w2.w;
        acc[12] += a * w3.x; acc[13] += a * w3.y; acc[14] += a * w3.z; acc[15] += a * w3.w;
    }

    float s = 0.f, tt = 0.f;
    #pragma unroll
    for (int c = 0; c < 16; c++) { s += acc[c] * a2s[c]; tt += acc[c] * a2d[c]; }
    g_s2[row] = s;
    g_t2[row] = tt;

    float4* hp = (float4*)&g_h2[row * 16];
    hp[0] = make_float4(acc[0],  acc[1],  acc[2],  acc[3]);
    hp[1] = make_float4(acc[4],  acc[5],  acc[6],  acc[7]);
    hp[2] = make_float4(acc[8],  acc[9],  acc[10], acc[11]);
    hp[3] = make_float4(acc[12], acc[13], acc[14], acc[15]);
}

// ---------------- Layer-2 aggregation + log_softmax fused ----------------
// Half-warp split: lanes 0-15 take even edges, 16-31 odd, combine via shfl.
__global__ void k_agg2(float* __restrict__ out) {
    int n = (blockIdx.x * blockDim.x + threadIdx.x) >> 5;
    if (n >= NN) return;
    const int lane = threadIdx.x & 31;
    const int ch = lane & 15;
    const int half = lane >> 4;

    const float tn = g_t2[n];
    const int j0 = g_off[n], j1 = g_off[n + 1];

    float d = 0.f, A = 0.f;
    #pragma unroll 2
    for (int j = j0 + half; j < j1; j += 2) {
        int src = __ldg(&g_srcs[j]);
        float e = __ldg(&g_s2[src]) + tn;
        e = e > 0.f ? e : 0.2f * e;
        float p = __expf(e);
        d += p;
        A += p * __ldg(&g_h2[src * 16 + ch]);
    }
    d += __shfl_xor_sync(0xffffffffu, d, 16);
    A += __shfl_xor_sync(0xffffffffu, A, 16);

    float l = A / (d + 1e-16f);

    float mx = l;
    #pragma unroll
    for (int o = 8; o; o >>= 1) mx = fmaxf(mx, __shfl_xor_sync(0xffffffffu, mx, o, 16));
    float ex = expf(l - mx);
    float sm = ex;
    #pragma unroll
    for (int o = 8; o; o >>= 1) sm += __shfl_xor_sync(0xffffffffu, sm, o, 16);
    float res = l - mx - logf(sm);
    if (lane < 16) out[n * 16 + ch] = res;
}

// ---------------- launch: CSR build on side stream overlapped with GEMM1 ----------------
static cudaStream_t g_side = 0;
static cudaEvent_t  g_evFork = 0, g_evJoin = 0;
static int g_res_ok = -1;

extern "C" void kernel_launch(void* const* d_in, const int* in_sizes, int n_in,
                              void* d_out, int out_size) {
    const float* x   = (const float*)d_in[0];
    const int*   ei  = (const int*)  d_in[1];
    const float* W1  = (const float*)d_in[2];
    const float* a1s = (const float*)d_in[3];
    const float* a1d = (const float*)d_in[4];
    const float* W2  = (const float*)d_in[5];
    const float* a2s = (const float*)d_in[6];
    const float* a2d = (const float*)d_in[7];
    float* out = (float*)d_out;

    if (g_res_ok < 0) {   // one-time resource creation (first call is uncaptured)
        cudaError_t e1 = cudaStreamCreateWithFlags(&g_side, cudaStreamNonBlocking);
        cudaError_t e2 = cudaEventCreateWithFlags(&g_evFork, cudaEventDisableTiming);
        cudaError_t e3 = cudaEventCreateWithFlags(&g_evJoin, cudaEventDisableTiming);
        g_res_ok = (e1 == cudaSuccess && e2 == cudaSuccess && e3 == cudaSuccess) ? 1 : 0;
    }
    cudaStream_t cs = (g_res_ok == 1) ? g_side : 0;

    if (g_res_ok == 1) {
        cudaEventRecord(g_evFork, 0);
        cudaStreamWaitEvent(g_side, g_evFork, 0);
    }

    // CSR build chain (independent of GEMM1)
    k_init    <<<(NN + 255) / 256, 256, 0, cs>>>(ei);
    k_hist    <<<(NE + 255) / 256, 256, 0, cs>>>(ei);
    k_scanA   <<<SCAN_B, 1024, 0, cs>>>();
    k_scanC   <<<(NN + 255) / 256, 256, 0, cs>>>();
    k_scatter <<<(NE + 255) / 256, 256, 0, cs>>>(ei);

    // GEMM1 on the capture stream, concurrent with CSR build
    k_gemm1   <<<(NN + 127) / 128, 128>>>(x, W1, a1s, a1d);

    if (g_res_ok == 1) {
        cudaEventRecord(g_evJoin, g_side);
        cudaStreamWaitEvent(0, g_evJoin, 0);
    }

    k_agg1    <<<(NN * 32 + 255) / 256, 256>>>();
    k_gemm2   <<<(NN + 127) / 128, 128>>>(W2, a2s, a2d);
    k_agg2    <<<(NN * 32 + 255) / 256, 256>>>(out);
}

// round 7
// speedup vs baseline: 1.0328x; 1.0328x over previous
#include <cuda_runtime.h>
#include <cstdint>
#include <math.h>

#define NN 100000
#define NE 1600000
#define SCAN_B 98   // ceil(NN/1024)

// ---------------- scratch (static device memory; no allocations) ----------------
__device__ int   g_is64;
__device__ int   g_deg[NN];
__device__ int   g_incl[NN];
__device__ int   g_bsum[SCAN_B];
__device__ int   g_off[NN + 1];
__device__ int   g_cur[NN];
__device__ int   g_srcs[NE];
__device__ float g_h1[NN * 64];
__device__ float g_s1[NN * 8];
__device__ float g_t1[NN * 8];
__device__ float g_z [NN * 64];
__device__ float g_h2[NN * 16];
__device__ float g_s2[NN];
__device__ float g_t2[NN];

// ---------------- init: zero counters + detect edge dtype (int64 vs int32) ----------------
__global__ void k_init(const int* __restrict__ w) {
    int i = blockIdx.x * blockDim.x + threadIdx.x;
    if (i < NN) { g_deg[i] = 0; g_cur[i] = 0; }
    if (i == 0) {
        int is64 = 1;
        #pragma unroll
        for (int k = 0; k < 8; k++)
            if (w[2 * k + 1] != 0) is64 = 0;
        g_is64 = is64;
    }
}

__global__ void k_hist(const int* __restrict__ w) {
    int i = blockIdx.x * blockDim.x + threadIdx.x;
    if (i >= NE) return;
    long long di = g_is64 ? 2LL * (NE + (long long)i) : (long long)(NE + i);
    atomicAdd(&g_deg[w[di]], 1);
}

__global__ void k_scanA() {
    __shared__ int sh[1024];
    int i = blockIdx.x * 1024 + threadIdx.x;
    int v = (i < NN) ? g_deg[i] : 0;
    sh[threadIdx.x] = v;
    __syncthreads();
    #pragma unroll
    for (int ofs = 1; ofs < 1024; ofs <<= 1) {
        int add = (threadIdx.x >= ofs) ? sh[threadIdx.x - ofs] : 0;
        __syncthreads();
        sh[threadIdx.x] += add;
        __syncthreads();
    }
    if (i < NN) g_incl[i] = sh[threadIdx.x];
    if (threadIdx.x == 1023) g_bsum[blockIdx.x] = sh[1023];
}

// fused: every block redundantly scans the 98 block sums, then writes its g_off slice.
__global__ void k_scanC() {
    __shared__ int sh[256];
    __shared__ int boff_s[256];
    int t = threadIdx.x;
    int v = (t < SCAN_B) ? g_bsum[t] : 0;
    sh[t] = v;
    __syncthreads();
    #pragma unroll
    for (int ofs = 1; ofs < 256; ofs <<= 1) {
        int add = (t >= ofs) ? sh[t - ofs] : 0;
        __syncthreads();
        sh[t] += add;
        __syncthreads();
    }
    boff_s[t] = sh[t] - v;    // exclusive prefix of block sums
    __syncthreads();

    int i = blockIdx.x * 256 + t;
    if (i < NN) g_off[i + 1] = g_incl[i] + boff_s[i >> 10];
    if (i == 0) g_off[0] = 0;
}

__global__ void k_scatter(const int* __restrict__ w) {
    int i = blockIdx.x * blockDim.x + threadIdx.x;
    if (i >= NE) return;
    int is64 = g_is64;
    int s = w[is64 ? 2LL * i : (long long)i];
    int d = w[is64 ? 2LL * (NE + (long long)i) : (long long)(NE + i)];
    int pos = g_off[d] + atomicAdd(&g_cur[d], 1);
    g_srcs[pos] = s;
}

// ---------------- GEMM1: h1 = x @ W1 (+ s1/t1 epilogue), packed f32x2 FFMA ----------------
// (round-3 proven version: single-ull LDS, 1 k per step)
__global__ __launch_bounds__(128, 4) void k_gemm1(
    const float* __restrict__ x, const float* __restrict__ W1,
    const float* __restrict__ a1s, const float* __restrict__ a1d)
{
    __shared__ unsigned long long xs[128][33];
    __shared__ __align__(16) float ws[32][64];
    const int t = threadIdx.x;
    const int rowblk = blockIdx.x * 128;
    const int tr = t >> 3;   // 0..15
    const int tc = t & 7;    // 0..7 (head)

    unsigned long long acc[8][4];
    #pragma unroll
    for (int r = 0; r < 8; r++)
        #pragma unroll
        for (int j = 0; j < 4; j++) acc[r][j] = 0ULL;

    for (int k0 = 0; k0 < 256; k0 += 32) {
        #pragma unroll
        for (int r = 0; r < 32; r++) {
            int row = (r << 2) + (t >> 5);
            int grow = rowblk + row;
            float v = (grow < NN) ? x[grow * 256 + k0 + (t & 31)] : 0.f;
            unsigned long long p;
            asm("mov.b64 %0, {%1, %1};" : "=l"(p) : "f"(v));
            xs[row][t & 31] = p;
        }
        #pragma unroll
        for (int r = 0; r < 16; r++) {
            int idx = (r << 7) + t;
            ws[idx >> 6][idx & 63] = W1[(k0 + (idx >> 6)) * 64 + (idx & 63)];
        }
        __syncthreads();
        #pragma unroll 8
        for (int k = 0; k < 32; k++) {
            const unsigned long long* bp = (const unsigned long long*)&ws[k][tc << 3];
            unsigned long long b0 = bp[0], b1 = bp[1], b2 = bp[2], b3 = bp[3];
            #pragma unroll
            for (int r = 0; r < 8; r++) {
                unsigned long long a2 = xs[tr + (r << 4)][k];
                asm("fma.rn.f32x2 %0, %4, %5, %0;\n\t"
                    "fma.rn.f32x2 %1, %4, %6, %1;\n\t"
                    "fma.rn.f32x2 %2, %4, %7, %2;\n\t"
                    "fma.rn.f32x2 %3, %4, %8, %3;"
                    : "+l"(acc[r][0]), "+l"(acc[r][1]), "+l"(acc[r][2]), "+l"(acc[r][3])
                    : "l"(a2), "l"(b0), "l"(b1), "l"(b2), "l"(b3));
            }
        }
        __syncthreads();
    }

    float av[8], bv[8];
    #pragma unroll
    for (int d = 0; d < 8; d++) { av[d] = a1s[(tc << 3) + d]; bv[d] = a1d[(tc << 3) + d]; }
    #pragma unroll
    for (int r = 0; r < 8; r++) {
        int grow = rowblk + tr + (r << 4);
        if (grow >= NN) continue;
        float s = 0.f, tt = 0.f;
        float2* hp = (float2*)&g_h1[grow * 64 + (tc << 3)];
        #pragma unroll
        for (int j = 0; j < 4; j++) {
            unsigned long long u = acc[r][j];
            float lo = __uint_as_float((unsigned)u);
            float hi = __uint_as_float((unsigned)(u >> 32));
            hp[j] = make_float2(lo, hi);
            s  += lo * av[2 * j] + hi * av[2 * j + 1];
            tt += lo * bv[2 * j] + hi * bv[2 * j + 1];
        }
        g_s1[grow * 8 + tc] = s;
        g_t1[grow * 8 + tc] = tt;
    }
}

// ---------------- Layer-1 aggregation: warp per dst node, 2 edges per iteration ----------------
// Lane layout: half = lane>>4 picks edge of the pair; q = lane&15 covers channels 4q..4q+3
// (one LDG.128 on h1); head = q>>1. Per 2 edges: 1 srcs LDG + 1 s1 LDG + 1 h1 LDG.128.
// Unshifted softmax (logits bounded) -> straight-line loop.
__global__ void k_agg1() {
    int n = (blockIdx.x * blockDim.x + threadIdx.x) >> 5;
    if (n >= NN) return;
    const int lane = threadIdx.x & 31;
    const int half = lane >> 4;       // which edge of the pair
    const int q    = lane & 15;       // channel quad: channels 4q..4q+3
    const int h    = q >> 1;          // head 0..7

    const float tn = g_t1[n * 8 + h];
    const int j0 = g_off[n], j1 = g_off[n + 1];

    float d = 0.f;
    float Ax = 0.f, Ay = 0.f, Az = 0.f, Aw = 0.f;

    for (int j = j0 + half; j < j1; j += 2) {
        int src = __ldg(&g_srcs[j]);
        float e = __ldg(&g_s1[src * 8 + h]) + tn;
        e = e > 0.f ? e : 0.2f * e;
        float p = __expf(e);
        float4 hv = *(const float4*)&g_h1[src * 64 + (q << 2)];
        d  += p;
        Ax += p * hv.x;
        Ay += p * hv.y;
        Az += p * hv.z;
        Aw += p * hv.w;
    }
    // combine the two half-warp partials (lane i pairs with i^16: same channels)
    d  += __shfl_xor_sync(0xffffffffu, d,  16);
    Ax += __shfl_xor_sync(0xffffffffu, Ax, 16);
    Ay += __shfl_xor_sync(0xffffffffu, Ay, 16);
    Az += __shfl_xor_sync(0xffffffffu, Az, 16);
    Aw += __shfl_xor_sync(0xffffffffu, Aw, 16);

    if (half == 0) {
        float inv = 1.f / (d + 1e-16f);
        float r0 = Ax * inv, r1 = Ay * inv, r2 = Az * inv, r3 = Aw * inv;
        float4 zo;
        zo.x = r0 > 0.f ? r0 : expm1f(r0);   // elu
        zo.y = r1 > 0.f ? r1 : expm1f(r1);
        zo.z = r2 > 0.f ? r2 : expm1f(r2);
        zo.w = r3 > 0.f ? r3 : expm1f(r3);
        *(float4*)&g_z[n * 64 + (q << 2)] = zo;
    }
}

// ---------------- GEMM2: h2 = z @ W2 (+ s2/t2 epilogue) ----------------
__global__ __launch_bounds__(128) void k_gemm2(
    const float* __restrict__ W2, const float* __restrict__ a2s, const float* __restrict__ a2d)
{
    __shared__ float zs[128][65];
    __shared__ __align__(16) float w2s[1024];
    const int t = threadIdx.x;
    const int base = blockIdx.x * 128;

    #pragma unroll
    for (int r = 0; r < 64; r++) {
        int i = (r << 7) + t;
        int row = i >> 6, col = i & 63;
        int grow = base + row;
        zs[row][col] = (grow < NN) ? g_z[grow * 64 + col] : 0.f;
    }
    #pragma unroll
    for (int r = 0; r < 8; r++) w2s[(r << 7) + t] = W2[(r << 7) + t];
    __syncthreads();

    int row = base + t;
    if (row >= NN) return;

    float acc[16];
    #pragma unroll
    for (int c = 0; c < 16; c++) acc[c] = 0.f;

    #pragma unroll 8
    for (int k = 0; k < 64; k++) {
        float a = zs[t][k];
        const float4* wp = (const float4*)&w2s[k << 4];
        float4 w0 = wp[0], w1 = wp[1], w2 = wp[2], w3 = wp[3];
        acc[0]  += a * w0.x; acc[1]  += a * w0.y; acc[2]  += a * w0.z; acc[3]  += a * w0.w;
        acc[4]  += a * w1.x; acc[5]  += a * w1.y; acc[6]  += a * w1.z; acc[7]  += a * w1.w;
        acc[8]  += a * w2.x; acc[9]  += a * w2.y; acc[10] += a * w2.z; acc[11] += a * w2.w;
        acc[12] += a * w3.x; acc[13] += a * w3.y; acc[14] += a * w3.z; acc[15] += a * w3.w;
    }

    float s = 0.f, tt = 0.f;
    #pragma unroll
    for (int c = 0; c < 16; c++) { s += acc[c] * a2s[c]; tt += acc[c] * a2d[c]; }
    g_s2[row] = s;
    g_t2[row] = tt;

    float4* hp = (float4*)&g_h2[row * 16];
    hp[0] = make_float4(acc[0],  acc[1],  acc[2],  acc[3]);
    hp[1] = make_float4(acc[4],  acc[5],  acc[6],  acc[7]);
    hp[2] = make_float4(acc[8],  acc[9],  acc[10], acc[11]);
    hp[3] = make_float4(acc[12], acc[13], acc[14], acc[15]);
}

// ---------------- Layer-2 aggregation + log_softmax fused ----------------
__global__ void k_agg2(float* __restrict__ out) {
    int n = (blockIdx.x * blockDim.x + threadIdx.x) >> 5;
    if (n >= NN) return;
    const int lane = threadIdx.x & 31;
    const int ch = lane & 15;
    const int half = lane >> 4;

    const float tn = g_t2[n];
    const int j0 = g_off[n], j1 = g_off[n + 1];

    float d = 0.f, A = 0.f;
    #pragma unroll 2
    for (int j = j0 + half; j < j1; j += 2) {
        int src = __ldg(&g_srcs[j]);
        float e = __ldg(&g_s2[src]) + tn;
        e = e > 0.f ? e : 0.2f * e;
        float p = __expf(e);
        d += p;
        A += p * __ldg(&g_h2[src * 16 + ch]);
    }
    d += __shfl_xor_sync(0xffffffffu, d, 16);
    A += __shfl_xor_sync(0xffffffffu, A, 16);

    float l = A / (d + 1e-16f);

    float mx = l;
    #pragma unroll
    for (int o = 8; o; o >>= 1) mx = fmaxf(mx, __shfl_xor_sync(0xffffffffu, mx, o, 16));
    float ex = expf(l - mx);
    float sm = ex;
    #pragma unroll
    for (int o = 8; o; o >>= 1) sm += __shfl_xor_sync(0xffffffffu, sm, o, 16);
    float res = l - mx - logf(sm);
    if (lane < 16) out[n * 16 + ch] = res;
}

// ---------------- launch: CSR build on side stream overlapped with GEMM1 ----------------
static cudaStream_t g_side = 0;
static cudaEvent_t  g_evFork = 0, g_evJoin = 0;
static int g_res_ok = -1;

extern "C" void kernel_launch(void* const* d_in, const int* in_sizes, int n_in,
                              void* d_out, int out_size) {
    const float* x   = (const float*)d_in[0];
    const int*   ei  = (const int*)  d_in[1];
    const float* W1  = (const float*)d_in[2];
    const float* a1s = (const float*)d_in[3];
    const float* a1d = (const float*)d_in[4];
    const float* W2  = (const float*)d_in[5];
    const float* a2s = (const float*)d_in[6];
    const float* a2d = (const float*)d_in[7];
    float* out = (float*)d_out;

    if (g_res_ok < 0) {   // one-time resource creation (first call is uncaptured)
        cudaError_t e1 = cudaStreamCreateWithFlags(&g_side, cudaStreamNonBlocking);
        cudaError_t e2 = cudaEventCreateWithFlags(&g_evFork, cudaEventDisableTiming);
        cudaError_t e3 = cudaEventCreateWithFlags(&g_evJoin, cudaEventDisableTiming);
        g_res_ok = (e1 == cudaSuccess && e2 == cudaSuccess && e3 == cudaSuccess) ? 1 : 0;
    }
    cudaStream_t cs = (g_res_ok == 1) ? g_side : 0;

    if (g_res_ok == 1) {
        cudaEventRecord(g_evFork, 0);
        cudaStreamWaitEvent(g_side, g_evFork, 0);
    }

    // CSR build chain (independent of GEMM1)
    k_init    <<<(NN + 255) / 256, 256, 0, cs>>>(ei);
    k_hist    <<<(NE + 255) / 256, 256, 0, cs>>>(ei);
    k_scanA   <<<SCAN_B, 1024, 0, cs>>>();
    k_scanC   <<<(NN + 255) / 256, 256, 0, cs>>>();
    k_scatter <<<(NE + 255) / 256, 256, 0, cs>>>(ei);

    // GEMM1 on the capture stream, concurrent with CSR build
    k_gemm1   <<<(NN + 127) / 128, 128>>>(x, W1, a1s, a1d);

    if (g_res_ok == 1) {
        cudaEventRecord(g_evJoin, g_side);
        cudaStreamWaitEvent(0, g_evJoin, 0);
    }

    k_agg1    <<<(NN * 32 + 255) / 256, 256>>>();
    k_gemm2   <<<(NN + 127) / 128, 128>>>(W2, a2s, a2d);
    k_agg2    <<<(NN * 32 + 255) / 256, 256>>>(out);
}

// round 9
// speedup vs baseline: 1.3135x; 1.2719x over previous
#include <cuda_runtime.h>
#include <cuda_bf16.h>
#include <cstdint>
#include <math.h>

#define NN 100000
#define NE 1600000
#define SCAN_B 98   // ceil(NN/1024)

// ---------------- scratch (static device memory; no allocations) ----------------
__device__ int   g_is64;
__device__ int   g_deg[NN];
__device__ int   g_incl[NN];
__device__ int   g_bsum[SCAN_B];
__device__ int   g_off[NN + 1];
__device__ int   g_cur[NN];
__device__ int   g_srcs[NE];
__device__ float g_h1[NN * 64];
__device__ float g_s1[NN * 8];
__device__ float g_t1[NN * 8];
__device__ float g_z [NN * 64];
__device__ float g_h2[NN * 16];
__device__ float g_s2[NN];
__device__ float g_t2[NN];
__device__ __nv_bfloat16 g_w1h[256 * 64];   // W1 split, [n][k] n-major
__device__ __nv_bfloat16 g_w1l[256 * 64];

// ---------------- init: zero counters + detect edge dtype (int64 vs int32) ----------------
__global__ void k_init(const int* __restrict__ w) {
    int i = blockIdx.x * blockDim.x + threadIdx.x;
    if (i < NN) { g_deg[i] = 0; g_cur[i] = 0; }
    if (i == 0) {
        int is64 = 1;
        #pragma unroll
        for (int k = 0; k < 8; k++)
            if (w[2 * k + 1] != 0) is64 = 0;
        g_is64 = is64;
    }
}

__global__ void k_hist(const int* __restrict__ w) {
    int i = blockIdx.x * blockDim.x + threadIdx.x;
    if (i >= NE) return;
    long long di = g_is64 ? 2LL * (NE + (long long)i) : (long long)(NE + i);
    atomicAdd(&g_deg[w[di]], 1);
}

__global__ void k_scanA() {
    __shared__ int sh[1024];
    int i = blockIdx.x * 1024 + threadIdx.x;
    int v = (i < NN) ? g_deg[i] : 0;
    sh[threadIdx.x] = v;
    __syncthreads();
    #pragma unroll
    for (int ofs = 1; ofs < 1024; ofs <<= 1) {
        int add = (threadIdx.x >= ofs) ? sh[threadIdx.x - ofs] : 0;
        __syncthreads();
        sh[threadIdx.x] += add;
        __syncthreads();
    }
    if (i < NN) g_incl[i] = sh[threadIdx.x];
    if (threadIdx.x == 1023) g_bsum[blockIdx.x] = sh[1023];
}

// fused: every block redundantly scans the 98 block sums, then writes its g_off slice.
__global__ void k_scanC() {
    __shared__ int sh[256];
    __shared__ int boff_s[256];
    int t = threadIdx.x;
    int v = (t < SCAN_B) ? g_bsum[t] : 0;
    sh[t] = v;
    __syncthreads();
    #pragma unroll
    for (int ofs = 1; ofs < 256; ofs <<= 1) {
        int add = (t >= ofs) ? sh[t - ofs] : 0;
        __syncthreads();
        sh[t] += add;
        __syncthreads();
    }
    boff_s[t] = sh[t] - v;    // exclusive prefix of block sums
    __syncthreads();

    int i = blockIdx.x * 256 + t;
    if (i < NN) g_off[i + 1] = g_incl[i] + boff_s[i >> 10];
    if (i == 0) g_off[0] = 0;
}

__global__ void k_scatter(const int* __restrict__ w) {
    int i = blockIdx.x * blockDim.x + threadIdx.x;
    if (i >= NE) return;
    int is64 = g_is64;
    int s = w[is64 ? 2LL * i : (long long)i];
    int d = w[is64 ? 2LL * (NE + (long long)i) : (long long)(NE + i)];
    int pos = g_off[d] + atomicAdd(&g_cur[d], 1);
    g_srcs[pos] = s;
}

// ---------------- W1 bf16 hi/lo split (once per call, tiny) ----------------
__global__ void k_prepW(const float* __restrict__ W1) {
    int i = blockIdx.x * blockDim.x + threadIdx.x;
    if (i >= 256 * 64) return;
    int k = i >> 6, n = i & 63;
    float v = W1[i];
    __nv_bfloat16 h = __float2bfloat16(v);
    __nv_bfloat16 l = __float2bfloat16(v - __bfloat162float(h));
    g_w1h[n * 256 + k] = h;
    g_w1l[n * 256 + k] = l;
}

// ---------------- GEMM1 on HMMA: h1 = x @ W1, bf16 3-term split ----------------
// mma.sync.m16n8k16 bf16, fp32 accumulate. Per block: 128 rows x 64 cols; 4 warps,
// warp w owns rows w*32..+31 (2 m16 tiles) x all 8 n8 tiles. K chunks of 32.
#define MMA16816(d, a, b0r, b1r) \
    asm volatile("mma.sync.aligned.m16n8k16.row.col.f32.bf16.bf16.f32 " \
        "{%0,%1,%2,%3}, {%4,%5,%6,%7}, {%8,%9}, {%0,%1,%2,%3};" \
        : "+f"((d)[0]), "+f"((d)[1]), "+f"((d)[2]), "+f"((d)[3]) \
        : "r"((a)[0]), "r"((a)[1]), "r"((a)[2]), "r"((a)[3]), "r"(b0r), "r"(b1r))

__global__ __launch_bounds__(128) void k_gemm1(
    const float* __restrict__ x,
    const float* __restrict__ a1s, const float* __restrict__ a1d)
{
    // stride 20 u32 -> frag LDS banks (20*(l>>2)+c)&31 all distinct: conflict-free
    __shared__ uint32_t xh[128][20], xl[128][20], wh[64][20], wl[64][20];
    const int t = threadIdx.x;
    const int w = t >> 5, l = t & 31;
    const int gid = l >> 2;   // groupID (row/col within fragment)
    const int c   = l & 3;    // thread-in-group (k pair / col pair)
    const int rowblk = blockIdx.x * 128;

    float acc[2][8][4];
    #pragma unroll
    for (int mt = 0; mt < 2; mt++)
        #pragma unroll
        for (int nt = 0; nt < 8; nt++)
            #pragma unroll
            for (int q = 0; q < 4; q++) acc[mt][nt][q] = 0.f;

    const uint32_t* wph = (const uint32_t*)g_w1h;
    const uint32_t* wpl = (const uint32_t*)g_w1l;

    for (int kc = 0; kc < 8; kc++) {
        // stage x chunk: 128 rows x 32 cols fp32 -> bf16 hi/lo packed pairs
        #pragma unroll
        for (int it = 0; it < 8; it++) {
            int f = (it << 7) + t;
            int row = f >> 3, c4 = f & 7;
            int grow = rowblk + row;
            float4 v = make_float4(0.f, 0.f, 0.f, 0.f);
            if (grow < NN) v = *(const float4*)&x[grow * 256 + (kc << 5) + (c4 << 2)];
            uint32_t uh0, uh1, ul0, ul1;
            asm("cvt.rn.bf16x2.f32 %0, %1, %2;" : "=r"(uh0) : "f"(v.y), "f"(v.x));
            asm("cvt.rn.bf16x2.f32 %0, %1, %2;" : "=r"(uh1) : "f"(v.w), "f"(v.z));
            float e0 = v.x - __uint_as_float(uh0 << 16);
            float e1 = v.y - __uint_as_float(uh0 & 0xffff0000u);
            float e2 = v.z - __uint_as_float(uh1 << 16);
            float e3 = v.w - __uint_as_float(uh1 & 0xffff0000u);
            asm("cvt.rn.bf16x2.f32 %0, %1, %2;" : "=r"(ul0) : "f"(e1), "f"(e0));
            asm("cvt.rn.bf16x2.f32 %0, %1, %2;" : "=r"(ul1) : "f"(e3), "f"(e2));
            xh[row][(c4 << 1)]     = uh0;
            xh[row][(c4 << 1) + 1] = uh1;
            xl[row][(c4 << 1)]     = ul0;
            xl[row][(c4 << 1) + 1] = ul1;
        }
        // stage W chunk: [64 n][16 kpairs] = 1024 entries -> 8 iterations of 128 threads
        #pragma unroll
        for (int it = 0; it < 8; it++) {
            int f = (it << 7) + t;
            int n = f >> 4, idx = f & 15;
            wh[n][idx] = wph[n * 128 + (kc << 4) + idx];
            wl[n][idx] = wpl[n * 128 + (kc << 4) + idx];
        }
        __syncthreads();

        #pragma unroll
        for (int ks = 0; ks < 2; ks++) {
            int kb = ks << 3;
            int r0 = (w << 5) + gid;
            uint32_t ah0[4] = { xh[r0][kb+c],    xh[r0+8][kb+c],    xh[r0][kb+c+4],    xh[r0+8][kb+c+4] };
            uint32_t ah1[4] = { xh[r0+16][kb+c], xh[r0+24][kb+c],   xh[r0+16][kb+c+4], xh[r0+24][kb+c+4] };
            uint32_t al0[4] = { xl[r0][kb+c],    xl[r0+8][kb+c],    xl[r0][kb+c+4],    xl[r0+8][kb+c+4] };
            uint32_t al1[4] = { xl[r0+16][kb+c], xl[r0+24][kb+c],   xl[r0+16][kb+c+4], xl[r0+24][kb+c+4] };
            #pragma unroll
            for (int nt = 0; nt < 8; nt++) {
                int n = (nt << 3) + gid;
                uint32_t bh0 = wh[n][kb+c], bh1 = wh[n][kb+c+4];
                uint32_t bl0 = wl[n][kb+c], bl1 = wl[n][kb+c+4];
                MMA16816(acc[0][nt], ah0, bh0, bh1);
                MMA16816(acc[1][nt], ah1, bh0, bh1);
                MMA16816(acc[0][nt], ah0, bl0, bl1);
                MMA16816(acc[1][nt], ah1, bl0, bl1);
                MMA16816(acc[0][nt], al0, bh0, bh1);
                MMA16816(acc[1][nt], al1, bh0, bh1);
            }
        }
        __syncthreads();
    }

    // ---- epilogue: store h1 + s1/t1 ----
    float as0[8], as1[8], ad0[8], ad1[8];
    #pragma unroll
    for (int nt = 0; nt < 8; nt++) {
        as0[nt] = __ldg(&a1s[(nt << 3) + (c << 1)]);
        as1[nt] = __ldg(&a1s[(nt << 3) + (c << 1) + 1]);
        ad0[nt] = __ldg(&a1d[(nt << 3) + (c << 1)]);
        ad1[nt] = __ldg(&a1d[(nt << 3) + (c << 1) + 1]);
    }
    #pragma unroll
    for (int mt = 0; mt < 2; mt++) {
        #pragma unroll
        for (int hf = 0; hf < 2; hf++) {
            int r = rowblk + (w << 5) + (mt << 4) + (hf << 3) + gid;
            bool ok = (r < NN);
            #pragma unroll
            for (int nt = 0; nt < 8; nt++) {
                float d0 = acc[mt][nt][(hf << 1)];
                float d1 = acc[mt][nt][(hf << 1) + 1];
                if (ok) *(float2*)&g_h1[r * 64 + (nt << 3) + (c << 1)] = make_float2(d0, d1);
                float sp = d0 * as0[nt] + d1 * as1[nt];
                float tp = d0 * ad0[nt] + d1 * ad1[nt];
                sp += __shfl_xor_sync(0xffffffffu, sp, 1);
                sp += __shfl_xor_sync(0xffffffffu, sp, 2);
                tp += __shfl_xor_sync(0xffffffffu, tp, 1);
                tp += __shfl_xor_sync(0xffffffffu, tp, 2);
                if (ok && c == 0) { g_s1[r * 8 + nt] = sp; g_t1[r * 8 + nt] = tp; }
            }
        }
    }
}

// ---------------- Layer-1 aggregation: warp per dst node, 2 edges per iteration ----------------
__global__ void k_agg1() {
    int n = (blockIdx.x * blockDim.x + threadIdx.x) >> 5;
    if (n >= NN) return;
    const int lane = threadIdx.x & 31;
    const int half = lane >> 4;       // which edge of the pair
    const int q    = lane & 15;       // channel quad: channels 4q..4q+3
    const int h    = q >> 1;          // head 0..7

    const float tn = g_t1[n * 8 + h];
    const int j0 = g_off[n], j1 = g_off[n + 1];

    float d = 0.f;
    float Ax = 0.f, Ay = 0.f, Az = 0.f, Aw = 0.f;

    for (int j = j0 + half; j < j1; j += 2) {
        int src = __ldg(&g_srcs[j]);
        float e = __ldg(&g_s1[src * 8 + h]) + tn;
        e = e > 0.f ? e : 0.2f * e;
        float p = __expf(e);
        float4 hv = *(const float4*)&g_h1[src * 64 + (q << 2)];
        d  += p;
        Ax += p * hv.x;
        Ay += p * hv.y;
        Az += p * hv.z;
        Aw += p * hv.w;
    }
    d  += __shfl_xor_sync(0xffffffffu, d,  16);
    Ax += __shfl_xor_sync(0xffffffffu, Ax, 16);
    Ay += __shfl_xor_sync(0xffffffffu, Ay, 16);
    Az += __shfl_xor_sync(0xffffffffu, Az, 16);
    Aw += __shfl_xor_sync(0xffffffffu, Aw, 16);

    if (half == 0) {
        float inv = 1.f / (d + 1e-16f);
        float r0 = Ax * inv, r1 = Ay * inv, r2 = Az * inv, r3 = Aw * inv;
        float4 zo;
        zo.x = r0 > 0.f ? r0 : expm1f(r0);   // elu
        zo.y = r1 > 0.f ? r1 : expm1f(r1);
        zo.z = r2 > 0.f ? r2 : expm1f(r2);
        zo.w = r3 > 0.f ? r3 : expm1f(r3);
        *(float4*)&g_z[n * 64 + (q << 2)] = zo;
    }
}

// ---------------- GEMM2: h2 = z @ W2 (+ s2/t2 epilogue) ----------------
__global__ __launch_bounds__(128) void k_gemm2(
    const float* __restrict__ W2, const float* __restrict__ a2s, const float* __restrict__ a2d)
{
    __shared__ float zs[128][65];
    __shared__ __align__(16) float w2s[1024];
    const int t = threadIdx.x;
    const int base = blockIdx.x * 128;

    #pragma unroll
    for (int r = 0; r < 64; r++) {
        int i = (r << 7) + t;
        int row = i >> 6, col = i & 63;
        int grow = base + row;
        zs[row][col] = (grow < NN) ? g_z[grow * 64 + col] : 0.f;
    }
    #pragma unroll
    for (int r = 0; r < 8; r++) w2s[(r << 7) + t] = W2[(r << 7) + t];
    __syncthreads();

    int row = base + t;
    if (row >= NN) return;

    float acc[16];
    #pragma unroll
    for (int cc = 0; cc < 16; cc++) acc[cc] = 0.f;

    #pragma unroll 8
    for (int k = 0; k < 64; k++) {
        float a = zs[t][k];
        const float4* wp = (const float4*)&w2s[k << 4];
        float4 w0 = wp[0], w1 = wp[1], w2 = wp[2], w3 = wp[3];
        acc[0]  += a * w0.x; acc[1]  += a * w0.y; acc[2]  += a * w0.z; acc[3]  += a * w0.w;
        acc[4]  += a * w1.x; acc[5]  += a * w1.y; acc[6]  += a * w1.z; acc[7]  += a * w1.w;
        acc[8]  += a * w2.x; acc[9]  += a * w2.y; acc[10] += a * w2.z; acc[11] += a * w2.w;
        acc[12] += a * w3.x; acc[13] += a * w3.y; acc[14] += a * w3.z; acc[15] += a * w3.w;
    }

    float s = 0.f, tt = 0.f;
    #pragma unroll
    for (int cc = 0; cc < 16; cc++) { s += acc[cc] * a2s[cc]; tt += acc[cc] * a2d[cc]; }
    g_s2[row] = s;
    g_t2[row] = tt;

    float4* hp = (float4*)&g_h2[row * 16];
    hp[0] = make_float4(acc[0],  acc[1],  acc[2],  acc[3]);
    hp[1] = make_float4(acc[4],  acc[5],  acc[6],  acc[7]);
    hp[2] = make_float4(acc[8],  acc[9],  acc[10], acc[11]);
    hp[3] = make_float4(acc[12], acc[13], acc[14], acc[15]);
}

// ---------------- Layer-2 aggregation + log_softmax fused ----------------
__global__ void k_agg2(float* __restrict__ out) {
    int n = (blockIdx.x * blockDim.x + threadIdx.x) >> 5;
    if (n >= NN) return;
    const int lane = threadIdx.x & 31;
    const int ch = lane & 15;
    const int half = lane >> 4;

    const float tn = g_t2[n];
    const int j0 = g_off[n], j1 = g_off[n + 1];

    float d = 0.f, A = 0.f;
    #pragma unroll 2
    for (int j = j0 + half; j < j1; j += 2) {
        int src = __ldg(&g_srcs[j]);
        float e = __ldg(&g_s2[src]) + tn;
        e = e > 0.f ? e : 0.2f * e;
        float p = __expf(e);
        d += p;
        A += p * __ldg(&g_h2[src * 16 + ch]);
    }
    d += __shfl_xor_sync(0xffffffffu, d, 16);
    A += __shfl_xor_sync(0xffffffffu, A, 16);

    float l = A / (d + 1e-16f);

    float mx = l;
    #pragma unroll
    for (int o = 8; o; o >>= 1) mx = fmaxf(mx, __shfl_xor_sync(0xffffffffu, mx, o, 16));
    float ex = expf(l - mx);
    float sm = ex;
    #pragma unroll
    for (int o = 8; o; o >>= 1) sm += __shfl_xor_sync(0xffffffffu, sm, o, 16);
    float res = l - mx - logf(sm);
    if (lane < 16) out[n * 16 + ch] = res;
}

// ---------------- launch: CSR build on side stream overlapped with GEMM1 ----------------
static cudaStream_t g_side = 0;
static cudaEvent_t  g_evFork = 0, g_evJoin = 0;
static int g_res_ok = -1;

extern "C" void kernel_launch(void* const* d_in, const int* in_sizes, int n_in,
                              void* d_out, int out_size) {
    const float* x   = (const float*)d_in[0];
    const int*   ei  = (const int*)  d_in[1];
    const float* W1  = (const float*)d_in[2];
    const float* a1s = (const float*)d_in[3];
    const float* a1d = (const float*)d_in[4];
    const float* W2  = (const float*)d_in[5];
    const float* a2s = (const float*)d_in[6];
    const float* a2d = (const float*)d_in[7];
    float* out = (float*)d_out;

    if (g_res_ok < 0) {   // one-time resource creation (first call is uncaptured)
        cudaError_t e1 = cudaStreamCreateWithFlags(&g_side, cudaStreamNonBlocking);
        cudaError_t e2 = cudaEventCreateWithFlags(&g_evFork, cudaEventDisableTiming);
        cudaError_t e3 = cudaEventCreateWithFlags(&g_evJoin, cudaEventDisableTiming);
        g_res_ok = (e1 == cudaSuccess && e2 == cudaSuccess && e3 == cudaSuccess) ? 1 : 0;
    }
    cudaStream_t cs = (g_res_ok == 1) ? g_side : 0;

    if (g_res_ok == 1) {
        cudaEventRecord(g_evFork, 0);
        cudaStreamWaitEvent(g_side, g_evFork, 0);
    }

    // CSR build chain (independent of GEMM1)
    k_init    <<<(NN + 255) / 256, 256, 0, cs>>>(ei);
    k_hist    <<<(NE + 255) / 256, 256, 0, cs>>>(ei);
    k_scanA   <<<SCAN_B, 1024, 0, cs>>>();
    k_scanC   <<<(NN + 255) / 256, 256, 0, cs>>>();
    k_scatter <<<(NE + 255) / 256, 256, 0, cs>>>(ei);

    // W split + GEMM1 (HMMA) on the capture stream, concurrent with CSR build
    k_prepW   <<<(256 * 64 + 255) / 256, 256>>>(W1);
    k_gemm1   <<<(NN + 127) / 128, 128>>>(x, a1s, a1d);

    if (g_res_ok == 1) {
        cudaEventRecord(g_evJoin, g_side);
        cudaStreamWaitEvent(0, g_evJoin, 0);
    }

    k_agg1    <<<(NN * 32 + 255) / 256, 256>>>();
    k_gemm2   <<<(NN + 127) / 128, 128>>>(W2, a2s, a2d);
    k_agg2    <<<(NN * 32 + 255) / 256, 256>>>(out);
}

// round 10
// speedup vs baseline: 1.3206x; 1.0054x over previous
#include <cuda_runtime.h>
#include <cuda_bf16.h>
#include <cuda_fp16.h>
#include <cstdint>
#include <math.h>

#define NN 100000
#define NE 1600000
#define SCAN_B 98   // ceil(NN/1024)

// ---------------- scratch (static device memory; no allocations) ----------------
__device__ int    g_is64;
__device__ int    g_deg[NN];
__device__ int    g_incl[NN];
__device__ int    g_bsum[SCAN_B];
__device__ int    g_off[NN + 1];
__device__ int    g_pos[NE];
__device__ int    g_srcs[NE];
__device__ __half g_h1[NN * 64];     // layer-1 features, fp16 (values only)
__device__ float  g_s1[NN * 8];
__device__ float  g_t1[NN * 8];
__device__ float  g_z [NN * 64];
__device__ __half g_h2[NN * 16];     // layer-2 features, fp16 (values only)
__device__ float  g_s2[NN];
__device__ float  g_t2[NN];
__device__ __nv_bfloat16 g_w1h[256 * 64];   // W1 split, [n][k] n-major
__device__ __nv_bfloat16 g_w1l[256 * 64];

// ---------------- init: zero counters + detect edge dtype (int64 vs int32) ----------------
__global__ void k_init(const int* __restrict__ w) {
    int i = blockIdx.x * blockDim.x + threadIdx.x;
    if (i < NN) g_deg[i] = 0;
    if (i == 0) {
        int is64 = 1;
        #pragma unroll
        for (int k = 0; k < 8; k++)
            if (w[2 * k + 1] != 0) is64 = 0;
        g_is64 = is64;
    }
}

// histogram + record each edge's slot within its dst segment (single atomic pass)
__global__ void k_hist(const int* __restrict__ w) {
    int i = blockIdx.x * blockDim.x + threadIdx.x;
    if (i >= NE) return;
    long long di = g_is64 ? 2LL * (NE + (long long)i) : (long long)(NE + i);
    g_pos[i] = atomicAdd(&g_deg[w[di]], 1);
}

__global__ void k_scanA() {
    __shared__ int sh[1024];
    int i = blockIdx.x * 1024 + threadIdx.x;
    int v = (i < NN) ? g_deg[i] : 0;
    sh[threadIdx.x] = v;
    __syncthreads();
    #pragma unroll
    for (int ofs = 1; ofs < 1024; ofs <<= 1) {
        int add = (threadIdx.x >= ofs) ? sh[threadIdx.x - ofs] : 0;
        __syncthreads();
        sh[threadIdx.x] += add;
        __syncthreads();
    }
    if (i < NN) g_incl[i] = sh[threadIdx.x];
    if (threadIdx.x == 1023) g_bsum[blockIdx.x] = sh[1023];
}

// fused: every block redundantly scans the 98 block sums, then writes its g_off slice.
__global__ void k_scanC() {
    __shared__ int sh[256];
    __shared__ int boff_s[256];
    int t = threadIdx.x;
    int v = (t < SCAN_B) ? g_bsum[t] : 0;
    sh[t] = v;
    __syncthreads();
    #pragma unroll
    for (int ofs = 1; ofs < 256; ofs <<= 1) {
        int add = (t >= ofs) ? sh[t - ofs] : 0;
        __syncthreads();
        sh[t] += add;
        __syncthreads();
    }
    boff_s[t] = sh[t] - v;    // exclusive prefix of block sums
    __syncthreads();

    int i = blockIdx.x * 256 + t;
    if (i < NN) g_off[i + 1] = g_incl[i] + boff_s[i >> 10];
    if (i == 0) g_off[0] = 0;
}

// pure gather+store, no atomics (slot precomputed in k_hist)
__global__ void k_scatter(const int* __restrict__ w) {
    int i = blockIdx.x * blockDim.x + threadIdx.x;
    if (i >= NE) return;
    int is64 = g_is64;
    int s = w[is64 ? 2LL * i : (long long)i];
    int d = w[is64 ? 2LL * (NE + (long long)i) : (long long)(NE + i)];
    g_srcs[g_off[d] + g_pos[i]] = s;
}

// ---------------- W1 bf16 hi/lo split (once per call, tiny) ----------------
__global__ void k_prepW(const float* __restrict__ W1) {
    int i = blockIdx.x * blockDim.x + threadIdx.x;
    if (i >= 256 * 64) return;
    int k = i >> 6, n = i & 63;
    float v = W1[i];
    __nv_bfloat16 h = __float2bfloat16(v);
    __nv_bfloat16 l = __float2bfloat16(v - __bfloat162float(h));
    g_w1h[n * 256 + k] = h;
    g_w1l[n * 256 + k] = l;
}

// ---------------- GEMM1 on HMMA: h1 = x @ W1, bf16 3-term split ----------------
#define MMA16816(d, a, b0r, b1r) \
    asm volatile("mma.sync.aligned.m16n8k16.row.col.f32.bf16.bf16.f32 " \
        "{%0,%1,%2,%3}, {%4,%5,%6,%7}, {%8,%9}, {%0,%1,%2,%3};" \
        : "+f"((d)[0]), "+f"((d)[1]), "+f"((d)[2]), "+f"((d)[3]) \
        : "r"((a)[0]), "r"((a)[1]), "r"((a)[2]), "r"((a)[3]), "r"(b0r), "r"(b1r))

__global__ __launch_bounds__(128) void k_gemm1(
    const float* __restrict__ x,
    const float* __restrict__ a1s, const float* __restrict__ a1d)
{
    // stride 20 u32 -> frag LDS banks (20*(l>>2)+c)&31 all distinct: conflict-free
    __shared__ uint32_t xh[128][20], xl[128][20], wh[64][20], wl[64][20];
    const int t = threadIdx.x;
    const int w = t >> 5, l = t & 31;
    const int gid = l >> 2;   // groupID (row/col within fragment)
    const int c   = l & 3;    // thread-in-group (k pair / col pair)
    const int rowblk = blockIdx.x * 128;

    float acc[2][8][4];
    #pragma unroll
    for (int mt = 0; mt < 2; mt++)
        #pragma unroll
        for (int nt = 0; nt < 8; nt++)
            #pragma unroll
            for (int q = 0; q < 4; q++) acc[mt][nt][q] = 0.f;

    const uint32_t* wph = (const uint32_t*)g_w1h;
    const uint32_t* wpl = (const uint32_t*)g_w1l;

    for (int kc = 0; kc < 8; kc++) {
        // stage x chunk: 128 rows x 32 cols fp32 -> bf16 hi/lo packed pairs
        #pragma unroll
        for (int it = 0; it < 8; it++) {
            int f = (it << 7) + t;
            int row = f >> 3, c4 = f & 7;
            int grow = rowblk + row;
            float4 v = make_float4(0.f, 0.f, 0.f, 0.f);
            if (grow < NN) v = *(const float4*)&x[grow * 256 + (kc << 5) + (c4 << 2)];
            uint32_t uh0, uh1, ul0, ul1;
            asm("cvt.rn.bf16x2.f32 %0, %1, %2;" : "=r"(uh0) : "f"(v.y), "f"(v.x));
            asm("cvt.rn.bf16x2.f32 %0, %1, %2;" : "=r"(uh1) : "f"(v.w), "f"(v.z));
            float e0 = v.x - __uint_as_float(uh0 << 16);
            float e1 = v.y - __uint_as_float(uh0 & 0xffff0000u);
            float e2 = v.z - __uint_as_float(uh1 << 16);
            float e3 = v.w - __uint_as_float(uh1 & 0xffff0000u);
            asm("cvt.rn.bf16x2.f32 %0, %1, %2;" : "=r"(ul0) : "f"(e1), "f"(e0));
            asm("cvt.rn.bf16x2.f32 %0, %1, %2;" : "=r"(ul1) : "f"(e3), "f"(e2));
            xh[row][(c4 << 1)]     = uh0;
            xh[row][(c4 << 1) + 1] = uh1;
            xl[row][(c4 << 1)]     = ul0;
            xl[row][(c4 << 1) + 1] = ul1;
        }
        // stage W chunk: [64 n][16 kpairs] = 1024 entries -> 8 iterations of 128 threads
        #pragma unroll
        for (int it = 0; it < 8; it++) {
            int f = (it << 7) + t;
            int n = f >> 4, idx = f & 15;
            wh[n][idx] = wph[n * 128 + (kc << 4) + idx];
            wl[n][idx] = wpl[n * 128 + (kc << 4) + idx];
        }
        __syncthreads();

        #pragma unroll
        for (int ks = 0; ks < 2; ks++) {
            int kb = ks << 3;
            int r0 = (w << 5) + gid;
            uint32_t ah0[4] = { xh[r0][kb+c],    xh[r0+8][kb+c],    xh[r0][kb+c+4],    xh[r0+8][kb+c+4] };
            uint32_t ah1[4] = { xh[r0+16][kb+c], xh[r0+24][kb+c],   xh[r0+16][kb+c+4], xh[r0+24][kb+c+4] };
            uint32_t al0[4] = { xl[r0][kb+c],    xl[r0+8][kb+c],    xl[r0][kb+c+4],    xl[r0+8][kb+c+4] };
            uint32_t al1[4] = { xl[r0+16][kb+c], xl[r0+24][kb+c],   xl[r0+16][kb+c+4], xl[r0+24][kb+c+4] };
            #pragma unroll
            for (int nt = 0; nt < 8; nt++) {
                int n = (nt << 3) + gid;
                uint32_t bh0 = wh[n][kb+c], bh1 = wh[n][kb+c+4];
                uint32_t bl0 = wl[n][kb+c], bl1 = wl[n][kb+c+4];
                MMA16816(acc[0][nt], ah0, bh0, bh1);
                MMA16816(acc[1][nt], ah1, bh0, bh1);
                MMA16816(acc[0][nt], ah0, bl0, bl1);
                MMA16816(acc[1][nt], ah1, bl0, bl1);
                MMA16816(acc[0][nt], al0, bh0, bh1);
                MMA16816(acc[1][nt], al1, bh0, bh1);
            }
        }
        __syncthreads();
    }

    // ---- epilogue: store h1 (fp16) + s1/t1 (fp32) ----
    float as0[8], as1[8], ad0[8], ad1[8];
    #pragma unroll
    for (int nt = 0; nt < 8; nt++) {
        as0[nt] = __ldg(&a1s[(nt << 3) + (c << 1)]);
        as1[nt] = __ldg(&a1s[(nt << 3) + (c << 1) + 1]);
        ad0[nt] = __ldg(&a1d[(nt << 3) + (c << 1)]);
        ad1[nt] = __ldg(&a1d[(nt << 3) + (c << 1) + 1]);
    }
    #pragma unroll
    for (int mt = 0; mt < 2; mt++) {
        #pragma unroll
        for (int hf = 0; hf < 2; hf++) {
            int r = rowblk + (w << 5) + (mt << 4) + (hf << 3) + gid;
            bool ok = (r < NN);
            #pragma unroll
            for (int nt = 0; nt < 8; nt++) {
                float d0 = acc[mt][nt][(hf << 1)];
                float d1 = acc[mt][nt][(hf << 1) + 1];
                if (ok) {
                    uint32_t hp;   // lo = d0 (ch), hi = d1 (ch+1)
                    asm("cvt.rn.f16x2.f32 %0, %1, %2;" : "=r"(hp) : "f"(d1), "f"(d0));
                    *(uint32_t*)&g_h1[r * 64 + (nt << 3) + (c << 1)] = hp;
                }
                float sp = d0 * as0[nt] + d1 * as1[nt];
                float tp = d0 * ad0[nt] + d1 * ad1[nt];
                sp += __shfl_xor_sync(0xffffffffu, sp, 1);
                sp += __shfl_xor_sync(0xffffffffu, sp, 2);
                tp += __shfl_xor_sync(0xffffffffu, tp, 1);
                tp += __shfl_xor_sync(0xffffffffu, tp, 2);
                if (ok && c == 0) { g_s1[r * 8 + nt] = sp; g_t1[r * 8 + nt] = tp; }
            }
        }
    }
}

// ---------------- Layer-1 aggregation: warp per dst node, 2 edges per iteration ----------------
// h1 gathered as fp16 (halves per-edge bytes); logits s1/t1 stay fp32 -> exact alphas.
__global__ void k_agg1() {
    int n = (blockIdx.x * blockDim.x + threadIdx.x) >> 5;
    if (n >= NN) return;
    const int lane = threadIdx.x & 31;
    const int half = lane >> 4;       // which edge of the pair
    const int q    = lane & 15;       // channel quad: channels 4q..4q+3
    const int h    = q >> 1;          // head 0..7

    const float tn = g_t1[n * 8 + h];
    const int j0 = g_off[n], j1 = g_off[n + 1];

    float d = 0.f;
    float Ax = 0.f, Ay = 0.f, Az = 0.f, Aw = 0.f;

    for (int j = j0 + half; j < j1; j += 2) {
        int src = __ldg(&g_srcs[j]);
        float e = __ldg(&g_s1[src * 8 + h]) + tn;
        e = e > 0.f ? e : 0.2f * e;
        float p = __expf(e);
        uint2 hv = __ldg((const uint2*)&g_h1[src * 64 + (q << 2)]);
        float2 f0 = __half22float2(*(const __half2*)&hv.x);
        float2 f1 = __half22float2(*(const __half2*)&hv.y);
        d  += p;
        Ax += p * f0.x;
        Ay += p * f0.y;
        Az += p * f1.x;
        Aw += p * f1.y;
    }
    d  += __shfl_xor_sync(0xffffffffu, d,  16);
    Ax += __shfl_xor_sync(0xffffffffu, Ax, 16);
    Ay += __shfl_xor_sync(0xffffffffu, Ay, 16);
    Az += __shfl_xor_sync(0xffffffffu, Az, 16);
    Aw += __shfl_xor_sync(0xffffffffu, Aw, 16);

    if (half == 0) {
        float inv = 1.f / (d + 1e-16f);
        float r0 = Ax * inv, r1 = Ay * inv, r2 = Az * inv, r3 = Aw * inv;
        float4 zo;
        zo.x = r0 > 0.f ? r0 : expm1f(r0);   // elu
        zo.y = r1 > 0.f ? r1 : expm1f(r1);
        zo.z = r2 > 0.f ? r2 : expm1f(r2);
        zo.w = r3 > 0.f ? r3 : expm1f(r3);
        *(float4*)&g_z[n * 64 + (q << 2)] = zo;
    }
}

// ---------------- GEMM2: h2 = z @ W2 (+ s2/t2 epilogue), h2 stored fp16 ----------------
__global__ __launch_bounds__(128) void k_gemm2(
    const float* __restrict__ W2, const float* __restrict__ a2s, const float* __restrict__ a2d)
{
    __shared__ float zs[128][65];
    __shared__ __align__(16) float w2s[1024];
    const int t = threadIdx.x;
    const int base = blockIdx.x * 128;

    #pragma unroll
    for (int r = 0; r < 64; r++) {
        int i = (r << 7) + t;
        int row = i >> 6, col = i & 63;
        int grow = base + row;
        zs[row][col] = (grow < NN) ? g_z[grow * 64 + col] : 0.f;
    }
    #pragma unroll
    for (int r = 0; r < 8; r++) w2s[(r << 7) + t] = W2[(r << 7) + t];
    __syncthreads();

    int row = base + t;
    if (row >= NN) return;

    float acc[16];
    #pragma unroll
    for (int cc = 0; cc < 16; cc++) acc[cc] = 0.f;

    #pragma unroll 8
    for (int k = 0; k < 64; k++) {
        float a = zs[t][k];
        const float4* wp = (const float4*)&w2s[k << 4];
        float4 w0 = wp[0], w1 = wp[1], w2 = wp[2], w3 = wp[3];
        acc[0]  += a * w0.x; acc[1]  += a * w0.y; acc[2]  += a * w0.z; acc[3]  += a * w0.w;
        acc[4]  += a * w1.x; acc[5]  += a * w1.y; acc[6]  += a * w1.z; acc[7]  += a * w1.w;
        acc[8]  += a * w2.x; acc[9]  += a * w2.y; acc[10] += a * w2.z; acc[11] += a * w2.w;
        acc[12] += a * w3.x; acc[13] += a * w3.y; acc[14] += a * w3.z; acc[15] += a * w3.w;
    }

    float s = 0.f, tt = 0.f;
    #pragma unroll
    for (int cc = 0; cc < 16; cc++) { s += acc[cc] * a2s[cc]; tt += acc[cc] * a2d[cc]; }
    g_s2[row] = s;
    g_t2[row] = tt;

    // pack 16 fp32 -> 16 fp16 (8 u32) -> 2x 16B stores
    uint32_t hp[8];
    #pragma unroll
    for (int cc = 0; cc < 8; cc++)
        asm("cvt.rn.f16x2.f32 %0, %1, %2;" : "=r"(hp[cc]) : "f"(acc[2*cc+1]), "f"(acc[2*cc]));
    uint4* op = (uint4*)&g_h2[row * 16];
    op[0] = make_uint4(hp[0], hp[1], hp[2], hp[3]);
    op[1] = make_uint4(hp[4], hp[5], hp[6], hp[7]);
}

// ---------------- Layer-2 aggregation + log_softmax fused ----------------
__global__ void k_agg2(float* __restrict__ out) {
    int n = (blockIdx.x * blockDim.x + threadIdx.x) >> 5;
    if (n >= NN) return;
    const int lane = threadIdx.x & 31;
    const int ch = lane & 15;
    const int half = lane >> 4;

    const float tn = g_t2[n];
    const int j0 = g_off[n], j1 = g_off[n + 1];

    float d = 0.f, A = 0.f;
    #pragma unroll 2
    for (int j = j0 + half; j < j1; j += 2) {
        int src = __ldg(&g_srcs[j]);
        float e = __ldg(&g_s2[src]) + tn;
        e = e > 0.f ? e : 0.2f * e;
        float p = __expf(e);
        d += p;
        A += p * __half2float(__ldg(&g_h2[src * 16 + ch]));
    }
    d += __shfl_xor_sync(0xffffffffu, d, 16);
    A += __shfl_xor_sync(0xffffffffu, A, 16);

    float l = A / (d + 1e-16f);

    float mx = l;
    #pragma unroll
    for (int o = 8; o; o >>= 1) mx = fmaxf(mx, __shfl_xor_sync(0xffffffffu, mx, o, 16));
    float ex = expf(l - mx);
    float sm = ex;
    #pragma unroll
    for (int o = 8; o; o >>= 1) sm += __shfl_xor_sync(0xffffffffu, sm, o, 16);
    float res = l - mx - logf(sm);
    if (lane < 16) out[n * 16 + ch] = res;
}

// ---------------- launch: CSR build on side stream overlapped with GEMM1 ----------------
static cudaStream_t g_side = 0;
static cudaEvent_t  g_evFork = 0, g_evJoin = 0;
static int g_res_ok = -1;

extern "C" void kernel_launch(void* const* d_in, const int* in_sizes, int n_in,
                              void* d_out, int out_size) {
    const float* x   = (const float*)d_in[0];
    const int*   ei  = (const int*)  d_in[1];
    const float* W1  = (const float*)d_in[2];
    const float* a1s = (const float*)d_in[3];
    const float* a1d = (const float*)d_in[4];
    const float* W2  = (const float*)d_in[5];
    const float* a2s = (const float*)d_in[6];
    const float* a2d = (const float*)d_in[7];
    float* out = (float*)d_out;

    if (g_res_ok < 0) {   // one-time resource creation (first call is uncaptured)
        cudaError_t e1 = cudaStreamCreateWithFlags(&g_side, cudaStreamNonBlocking);
        cudaError_t e2 = cudaEventCreateWithFlags(&g_evFork, cudaEventDisableTiming);
        cudaError_t e3 = cudaEventCreateWithFlags(&g_evJoin, cudaEventDisableTiming);
        g_res_ok = (e1 == cudaSuccess && e2 == cudaSuccess && e3 == cudaSuccess) ? 1 : 0;
    }
    cudaStream_t cs = (g_res_ok == 1) ? g_side : 0;

    if (g_res_ok == 1) {
        cudaEventRecord(g_evFork, 0);
        cudaStreamWaitEvent(g_side, g_evFork, 0);
    }

    // CSR build chain (independent of GEMM1)
    k_init    <<<(NN + 255) / 256, 256, 0, cs>>>(ei);
    k_hist    <<<(NE + 255) / 256, 256, 0, cs>>>(ei);
    k_scanA   <<<SCAN_B, 1024, 0, cs>>>();
    k_scanC   <<<(NN + 255) / 256, 256, 0, cs>>>();
    k_scatter <<<(NE + 255) / 256, 256, 0, cs>>>(ei);

    // W split + GEMM1 (HMMA) on the capture stream, concurrent with CSR build
    k_prepW   <<<(256 * 64 + 255) / 256, 256>>>(W1);
    k_gemm1   <<<(NN + 127) / 128, 128>>>(x, a1s, a1d);

    if (g_res_ok == 1) {
        cudaEventRecord(g_evJoin, g_side);
        cudaStreamWaitEvent(0, g_evJoin, 0);
    }

    k_agg1    <<<(NN * 32 + 255) / 256, 256>>>();
    k_gemm2   <<<(NN + 127) / 128, 128>>>(W2, a2s, a2d);
    k_agg2    <<<(NN * 32 + 255) / 256, 256>>>(out);
}